// round 11
// baseline (speedup 1.0000x reference)
#include <cuda_runtime.h>
#include <math.h>

// Problem constants
#define NB 8
#define NK 1024
#define NL 1024
#define ND 1024
#define NO 6
#define NE 128

// Scratch (tiny): everything l-independent
__device__ __align__(16) float g_S [NB*NO*NE];   // raw vote sum   [b,o,e]
__device__ __align__(16) float g_Wv[NB*NO*ND];   // W @ v          [b,o,d]
__device__ __align__(16) float g_a [NB*NK*NO];   // logits         [b,k,o]
__device__ __align__(16) float g_p [NB*NK*NO];   // probs          [b,k,o]
__device__ __align__(16) float g_pu[NB*NO*ND];   // p^T @ u        [b,o,d]
__device__ int g_mask_is_u8;                     // mask dtype flag

// ---------------------------------------------------------------------------
// Prolog: zero g_pu & g_S, detect mask dtype.
__global__ void k_prolog(const unsigned char* __restrict__ mraw) {
    int i = blockIdx.x * 256 + threadIdx.x;
    if (i < NB*NO*ND) g_pu[i] = 0.f;
    if (i < NB*NO*NE) g_S[i]  = 0.f;
    if (blockIdx.x == 0 && threadIdx.x == 0) {
        int u8 = 0;
        for (int j = 0; j < 256; j++)
            if ((j & 3) != 0 && mraw[j] != 0) u8 = 1;
        g_mask_is_u8 = u8;
    }
}

__device__ __forceinline__ int mask_at(const unsigned char* mraw, size_t idx) {
    if (g_mask_is_u8) return mraw[idx] != 0;
    return ((const int*)mraw)[idx] != 0;
}

// ---------------------------------------------------------------------------
// Iteration-0 shortcut: p0 = 1/6 uniform, so pu0[b,o,d] = (1/6)*sum_k u —
// o-independent. colsum into g_pu[b][0][:]. float4: thread owns 4 d's.
// grid (NB, 32) = 256 blocks, block 256; k-chunk = 32.
__global__ void k_colsum(const float* __restrict__ u) {
    int b  = blockIdx.x;
    int kb = blockIdx.y * 32;
    const float4* up4 = (const float4*)(u + ((size_t)b * NK + kb) * ND) + threadIdx.x;
    float4 acc = make_float4(0.f, 0.f, 0.f, 0.f);
#pragma unroll 8
    for (int kk = 0; kk < 32; kk++) {
        float4 uv = up4[kk * (ND / 4)];
        acc.x += uv.x; acc.y += uv.y; acc.z += uv.z; acc.w += uv.w;
    }
    float* dst = &g_pu[(size_t)b * NO * ND + threadIdx.x * 4];
    atomicAdd(dst + 0, acc.x);
    atomicAdd(dst + 1, acc.y);
    atomicAdd(dst + 2, acc.z);
    atomicAdd(dst + 3, acc.w);
}

// ---------------------------------------------------------------------------
// S[b,o,e] += sum_{d in 16-chunk} pu[b,o,d] * W[o,d,e] for all 8 b at once.
// FIRST: read o-independent colsum (o=0 row) scaled by 1/6.
// grid (NO, ND/16), block 128.
template <int FIRST>
__global__ void k_S(const float* __restrict__ W) {
    __shared__ float spu[NB][16];
    int o  = blockIdx.x;
    int dc = blockIdx.y * 16;
    int e  = threadIdx.x;

    {   // 128 threads load exactly 128 entries
        int b = threadIdx.x >> 4, dd = threadIdx.x & 15;
        float v = FIRST ? g_pu[(size_t)b * NO * ND + dc + dd] * (1.f / 6.f)
                        : g_pu[((size_t)b * NO + o) * ND + dc + dd];
        spu[b][dd] = v;
    }
    __syncthreads();

    float acc[NB];
#pragma unroll
    for (int b = 0; b < NB; b++) acc[b] = 0.f;

    const float* Wo = W + ((size_t)o * ND + dc) * NE + e;
#pragma unroll
    for (int dd = 0; dd < 16; dd++) {
        float w = Wo[(size_t)dd * NE];
#pragma unroll
        for (int b = 0; b < NB; b++) acc[b] += spu[b][dd] * w;
    }
#pragma unroll
    for (int b = 0; b < NB; b++)
        atomicAdd(&g_S[((size_t)b * NO + o) * NE + e], acc[b]);
}

// ---------------------------------------------------------------------------
// Fused squash + Wv: v = squash(S) per-block, then Wv[b,o,d] =
// sum_e W[o,d,e]*v[b,o,e] for all 8 b. float4 W + v loads.
// Also zeroes g_pu for the next k_apu (768 blocks x 64 floats).
// grid (NO, ND/8), block 256 = 8 warps (warp = one d)
__global__ void k_WvSq(const float* __restrict__ W) {
    __shared__ __align__(16) float sv[NB][NE];   // 4 KB
    __shared__ float sfac[NB];
    int o = blockIdx.x;
    int wid = threadIdx.x >> 5, lane = threadIdx.x & 31;

    // zero g_pu slice: 49152 / 768 blocks = 64 floats per block
    {
        int slice = blockIdx.x * (ND / 8) + blockIdx.y;   // 0..767
        if (threadIdx.x < 64) g_pu[(size_t)slice * 64 + threadIdx.x] = 0.f;
    }

    for (int i = threadIdx.x; i < NB * NE; i += 256)
        sv[i >> 7][i & 127] = g_S[((size_t)(i >> 7) * NO + o) * NE + (i & 127)];
    __syncthreads();

    // warp w computes squash factor for b=w
    {
        float sq = 0.f;
#pragma unroll
        for (int j = 0; j < 4; j++) {
            float x = sv[wid][lane + 32 * j];
            sq += x * x;
        }
#pragma unroll
        for (int off = 16; off; off >>= 1) sq += __shfl_xor_sync(0xffffffffu, sq, off);
        if (lane == 0) sfac[wid] = sq / (1.f + sq) / (sqrtf(sq) + 1e-8f);
    }
    __syncthreads();
    for (int i = threadIdx.x; i < NB * NE; i += 256)
        sv[i >> 7][i & 127] *= sfac[i >> 7];
    __syncthreads();

    int d = blockIdx.y * 8 + wid;
    const float4* Wrow4 = (const float4*)(W + ((size_t)o * ND + d) * NE);
    float4 wv = Wrow4[lane];

#pragma unroll
    for (int b = 0; b < NB; b++) {
        float4 vv = ((const float4*)sv[b])[lane];
        float s = wv.x * vv.x + wv.y * vv.y + wv.z * vv.z + wv.w * vv.w;
#pragma unroll
        for (int off = 16; off; off >>= 1) s += __shfl_xor_sync(0xffffffffu, s, off);
        if (lane == 0) g_Wv[((size_t)b * NO + o) * ND + d] = s;
    }
}

// ---------------------------------------------------------------------------
// Fused agreement + softmax + pu-accumulation (float4 loads):
//  phase 1: a[b,k,o] (+)= sum_d u[b,k,d]*Wv[b,o,d]; p = masked softmax
//  phase 2: pu[b,o,d] += sum_{k in block} p[k,o]*u[b,k,d]  (u hot in L1/L2)
// Also zeroes g_S slices for the next k_S.
// grid (NB, NK/16) = 512 blocks, block 256 = 8 warps, each warp does 2 k's.
template <int ACCUM>
__global__ void k_apu(const float* __restrict__ u,
                      const unsigned char* __restrict__ mraw) {
    __shared__ __align__(16) float sWv[NO * ND];  // 24 KB
    __shared__ float sp[16][NO];
    int b  = blockIdx.x;
    int kb = blockIdx.y * 16;

    // zero g_S slice: 6144 / 512 blocks = 12 floats each
    {
        int slice = blockIdx.x * 64 + blockIdx.y;   // 0..511
        if (threadIdx.x < 12) g_S[(size_t)slice * 12 + threadIdx.x] = 0.f;
    }

    for (int i = threadIdx.x; i < NO * ND; i += 256)
        sWv[i] = g_Wv[(size_t)b * NO * ND + i];
    __syncthreads();

    int warp = threadIdx.x >> 5, lane = threadIdx.x & 31;

    for (int ki = 0; ki < 2; ki++) {
        int k = kb + warp * 2 + ki;
        const float4* urow4 = (const float4*)(u + ((size_t)b * NK + k) * ND);
        float av[NO];
#pragma unroll
        for (int o = 0; o < NO; o++) av[o] = 0.f;
#pragma unroll
        for (int j = 0; j < 8; j++) {
            float4 uv = urow4[lane + 32 * j];
            int d0 = 4 * lane + 128 * j;
#pragma unroll
            for (int o = 0; o < NO; o++) {
                float4 wv = *(const float4*)&sWv[o * ND + d0];
                av[o] += uv.x * wv.x + uv.y * wv.y + uv.z * wv.z + uv.w * wv.w;
            }
        }
#pragma unroll
        for (int off = 16; off; off >>= 1) {
#pragma unroll
            for (int o = 0; o < NO; o++)
                av[o] += __shfl_xor_sync(0xffffffffu, av[o], off);
        }
        if (lane == 0) {
            size_t base = ((size_t)b * NK + k) * NO;
            if (ACCUM) {
#pragma unroll
                for (int o = 0; o < NO; o++) av[o] += g_a[base + o];
            }
#pragma unroll
            for (int o = 0; o < NO; o++) g_a[base + o] = av[o];

            float pr[NO];
            if (mask_at(mraw, (size_t)b * NK + k)) {
#pragma unroll
                for (int o = 0; o < NO; o++) pr[o] = 1.f / 6.f;
            } else {
                float m = av[0];
#pragma unroll
                for (int o = 1; o < NO; o++) m = fmaxf(m, av[o]);
                float ssum = 0.f;
#pragma unroll
                for (int o = 0; o < NO; o++) { pr[o] = expf(av[o] - m); ssum += pr[o]; }
                float inv = 1.f / ssum;
#pragma unroll
                for (int o = 0; o < NO; o++) pr[o] *= inv;
            }
#pragma unroll
            for (int o = 0; o < NO; o++) {
                g_p[base + o] = pr[o];
                sp[warp * 2 + ki][o] = pr[o];
            }
        }
    }
    __syncthreads();

    // phase 2: pu += p^T u over this block's 16 k rows; thread owns 4 d's
    {
        const float4* up4 = (const float4*)(u + ((size_t)b * NK + kb) * ND) + threadIdx.x;
        float4 acc[NO];
#pragma unroll
        for (int o = 0; o < NO; o++) acc[o] = make_float4(0.f, 0.f, 0.f, 0.f);
#pragma unroll 4
        for (int kk = 0; kk < 16; kk++) {
            float4 uv = up4[kk * (ND / 4)];
#pragma unroll
            for (int o = 0; o < NO; o++) {
                float pk = sp[kk][o];
                acc[o].x += pk * uv.x; acc[o].y += pk * uv.y;
                acc[o].z += pk * uv.z; acc[o].w += pk * uv.w;
            }
        }
#pragma unroll
        for (int o = 0; o < NO; o++) {
            float* dst = &g_pu[((size_t)b * NO + o) * ND + threadIdx.x * 4];
            atomicAdd(dst + 0, acc[o].x);
            atomicAdd(dst + 1, acc[o].y);
            atomicAdd(dst + 2, acc[o].z);
            atomicAdd(dst + 3, acc[o].w);
        }
    }
}

// ---------------------------------------------------------------------------
// probs broadcast: probs[b,l,k,o] = p[b,k,o].  grid (NB, NL/16), block 256
__global__ void k_out_p(float4* __restrict__ outp) {
    __shared__ float4 spp[NK * NO / 4];  // 1536 float4 = 24 KB
    int b  = blockIdx.x;
    int lb = blockIdx.y * 16;
    const float4* psrc = (const float4*)(g_p + (size_t)b * NK * NO);
    for (int i = threadIdx.x; i < 1536; i += 256) spp[i] = psrc[i];
    __syncthreads();
    for (int l = 0; l < 16; l++) {
        float4* dst = outp + ((size_t)b * NL + lb + l) * 1536;
#pragma unroll 2
        for (int i = threadIdx.x; i < 1536; i += 256) dst[i] = spp[i];
    }
}

// outputs_v broadcast: squash(S) fused. grid (NB, NL/16), block 256
__global__ void k_out_v(float4* __restrict__ outv) {
    __shared__ __align__(16) float sv[NO * NE];  // 768 floats
    __shared__ float sfac[NO];
    int b  = blockIdx.x;
    int lb = blockIdx.y * 16;
    int wid = threadIdx.x >> 5, lane = threadIdx.x & 31;

    for (int i = threadIdx.x; i < NO * NE; i += 256)
        sv[i] = g_S[(size_t)b * NO * NE + i];
    __syncthreads();

    if (wid < NO) {
        float sq = 0.f;
#pragma unroll
        for (int j = 0; j < 4; j++) {
            float x = sv[wid * NE + lane + 32 * j];
            sq += x * x;
        }
#pragma unroll
        for (int off = 16; off; off >>= 1) sq += __shfl_xor_sync(0xffffffffu, sq, off);
        if (lane == 0) sfac[wid] = sq / (1.f + sq) / (sqrtf(sq) + 1e-8f);
    }
    __syncthreads();
    for (int i = threadIdx.x; i < NO * NE; i += 256)
        sv[i] *= sfac[i >> 7];
    __syncthreads();

    const float4* sv4 = (const float4*)sv;
    for (int idx = threadIdx.x; idx < 16 * 192; idx += 256) {
        int l = idx / 192, c = idx % 192;
        outv[((size_t)b * NL + lb + l) * 192 + c] = sv4[c];
    }
}

// ---------------------------------------------------------------------------
extern "C" void kernel_launch(void* const* d_in, const int* in_sizes, int n_in,
                              void* d_out, int out_size) {
    const float*         u    = (const float*)d_in[0];
    // d_in[1] = context_sequence: unused (result is independent of L content)
    const float*         W    = (const float*)d_in[2];
    const unsigned char* mask = (const unsigned char*)d_in[3];

    float* out   = (float*)d_out;
    float4* outv = (float4*)out;                               // [B,L,O,E]
    float4* outp = (float4*)(out + (size_t)NB * NL * NO * NE); // [B,L,K,O]

    // Side stream + events for the output fork-join (host-side resources only;
    // created once, identical work per call).
    static cudaStream_t s2 = [] {
        cudaStream_t s; cudaStreamCreateWithFlags(&s, cudaStreamNonBlocking); return s;
    }();
    static cudaEvent_t e1 = [] {
        cudaEvent_t e; cudaEventCreateWithFlags(&e, cudaEventDisableTiming); return e;
    }();
    static cudaEvent_t e2 = [] {
        cudaEvent_t e; cudaEventCreateWithFlags(&e, cudaEventDisableTiming); return e;
    }();

    dim3 b256(256);
    dim3 gCS(NB, 32);
    dim3 gS(NO, ND / 16);
    dim3 gWv(NO, ND / 8);
    dim3 gAP(NB, NK / 16);
    dim3 gOUT(NB, NL / 16);

    // iteration 0: uniform p -> colsum shortcut
    k_prolog<<<192, b256>>>(mask);
    k_colsum<<<gCS, b256>>>(u);
    k_S<1><<<gS, 128>>>(W);
    k_WvSq<<<gWv, b256>>>(W);                   // v0 -> Wv0; zero pu
    k_apu<0><<<gAP, b256>>>(u, mask);           // a=u.Wv0, p1, pu1; zero S

    // iteration 1
    k_S<0><<<gS, 128>>>(W);
    k_WvSq<<<gWv, b256>>>(W);                   // v1 -> Wv1; zero pu
    k_apu<1><<<gAP, b256>>>(u, mask);           // a+=u.Wv1, p2, pu2; zero S

    // fork: p2 is final -> broadcast probs on side stream while S2 computes
    cudaEventRecord(e1, 0);
    cudaStreamWaitEvent(s2, e1, 0);
    k_out_p<<<gOUT, b256, 0, s2>>>(outp);

    // iteration 2 (final) on main stream: S2 then squash+v broadcast
    k_S<0><<<gS, 128>>>(W);
    k_out_v<<<gOUT, b256>>>(outv);

    // join
    cudaEventRecord(e2, s2);
    cudaStreamWaitEvent(0, e2, 0);

    (void)in_sizes; (void)n_in; (void)out_size;
}